// round 6
// baseline (speedup 1.0000x reference)
#include <cuda_runtime.h>
#include <cstdint>

#define D_DIM 64
#define BT 32            // b per block
#define NT 64            // n per block
#define TPB 128
#define XSTRIDE 68       // floats; 16B-aligned row stride, conflict-free
#define ASTRIDE 68

// ---- packed f32x2 helpers (Blackwell FFMA2 path) ----
__device__ __forceinline__ uint64_t pk2(float lo, float hi) {
    uint64_t r; asm("mov.b64 %0, {%1, %2};" : "=l"(r) : "f"(lo), "f"(hi)); return r;
}
__device__ __forceinline__ void upk2(uint64_t v, float& lo, float& hi) {
    asm("mov.b64 {%0, %1}, %2;" : "=f"(lo), "=f"(hi) : "l"(v));
}
__device__ __forceinline__ uint64_t fma2(uint64_t a, uint64_t b, uint64_t c) {
    uint64_t d; asm("fma.rn.f32x2 %0, %1, %2, %3;" : "=l"(d) : "l"(a), "l"(b), "l"(c)); return d;
}
__device__ __forceinline__ uint64_t mul2(uint64_t a, uint64_t b) {
    uint64_t d; asm("mul.rn.f32x2 %0, %1, %2;" : "=l"(d) : "l"(a), "l"(b)); return d;
}
__device__ __forceinline__ uint64_t add2(uint64_t a, uint64_t b) {
    uint64_t d; asm("add.rn.f32x2 %0, %1, %2;" : "=l"(d) : "l"(a), "l"(b)); return d;
}

extern __shared__ float smem_dyn[];

// One 4-dim block: 2 b x 8 n per thread (4 packed n-pairs).
__device__ __forceinline__ void do_dblk(const float* __restrict__ xrow,
                                        const float* __restrict__ arow,
                                        const float* __restrict__ brow,
                                        int dblk, uint64_t M1,
                                        uint64_t (&sacc)[2][4],
                                        uint64_t (&pacc)[2][4])
{
    float4 xv0 = *reinterpret_cast<const float4*>(xrow + dblk);
    float4 xv1 = *reinterpret_cast<const float4*>(xrow + XSTRIDE + dblk);
    const float x0[4] = {xv0.x, xv0.y, xv0.z, xv0.w};
    const float x1[4] = {xv1.x, xv1.y, xv1.z, xv1.w};

    #pragma unroll
    for (int dd = 0; dd < 4; dd++) {
        const int off = (dblk + dd) * ASTRIDE;
        const ulonglong2 a01 = *reinterpret_cast<const ulonglong2*>(arow + off);
        const ulonglong2 a23 = *reinterpret_cast<const ulonglong2*>(arow + off + 4);
        const ulonglong2 b01 = *reinterpret_cast<const ulonglong2*>(brow + off);
        const ulonglong2 b23 = *reinterpret_cast<const ulonglong2*>(brow + off + 4);
        const uint64_t A[4]  = {a01.x, a01.y, a23.x, a23.y};
        const uint64_t Bv[4] = {b01.x, b01.y, b23.x, b23.y};

        const uint64_t xp0 = pk2(x0[dd], x0[dd]);   // 1 pk2 feeds 16 FFMA2
        const uint64_t xp1 = pk2(x1[dd], x1[dd]);
        #pragma unroll
        for (int k = 0; k < 4; k++) {
            uint64_t z0 = fma2(xp0, A[k], Bv[k]);
            uint64_t z1 = fma2(xp1, A[k], Bv[k]);
            uint64_t w0 = fma2(z0, z0, M1);          // z^2 - 1
            uint64_t w1 = fma2(z1, z1, M1);
            sacc[0][k] = add2(sacc[0][k], w0);       // sum z^2 = sum w + count
            sacc[1][k] = add2(sacc[1][k], w1);
            pacc[0][k] = mul2(pacc[0][k], w0);
            pacc[1][k] = mul2(pacc[1][k], w1);
        }
    }
}

__global__ __launch_bounds__(TPB)
void wavelet_kernel(const float* __restrict__ x,
                    const float* __restrict__ centers,
                    const float* __restrict__ scales,
                    float* __restrict__ out, int N)
{
    float* sx = smem_dyn;                   // [BT][XSTRIDE]  b-major
    float* sa = sx + BT * XSTRIDE;          // [D][ASTRIDE]   d-major: 1/s
    float* sb = sa + D_DIM * ASTRIDE;       // [D][ASTRIDE]   -c/s

    const int tid = threadIdx.x;
    const int b0 = blockIdx.x * BT;
    const int n0 = blockIdx.y * NT;

    // x tile (coalesced)
    #pragma unroll 4
    for (int i = tid; i < BT * D_DIM; i += TPB) {
        int r = i >> 6, c = i & 63;
        sx[r * XSTRIDE + c] = x[(b0 + r) * D_DIM + c];
    }
    // a/b tiles, transposed to [d][n]
    #pragma unroll 8
    for (int i = tid; i < NT * D_DIM; i += TPB) {
        int d = i & 63, n = i >> 6;
        int g = (n0 + n) * D_DIM + d;
        float inv = 1.0f / scales[g];
        sa[d * ASTRIDE + n] = inv;
        sb[d * ASTRIDE + n] = -centers[g] * inv;
    }
    __syncthreads();

    const int ng = tid & 7;    // 8 n's at ng*8 (4 packed pairs)
    const int bg = tid >> 3;   // 2 b's at bg*2

    const float* xrow = sx + (bg * 2) * XSTRIDE;
    const float* arow = sa + ng * 8;
    const float* brow = sb + ng * 8;

    const uint64_t M1 = pk2(-1.0f, -1.0f);
    uint64_t sacc[2][4], pacc[2][4];
    #pragma unroll
    for (int bi = 0; bi < 2; bi++)
        #pragma unroll
        for (int k = 0; k < 4; k++) { sacc[bi][k] = pk2(0.f, 0.f); pacc[bi][k] = pk2(1.f, 1.f); }

    // first half: d = 0..31
    #pragma unroll 1
    for (int dblk = 0; dblk < 32; dblk += 4)
        do_dblk(xrow, arow, brow, dblk, M1, sacc, pacc);

    // range-control fold: Gaussian factor for first 32 dims
    #pragma unroll
    for (int bi = 0; bi < 2; bi++)
        #pragma unroll
        for (int k = 0; k < 4; k++) {
            float s0, s1, p0, p1;
            upk2(sacc[bi][k], s0, s1);
            upk2(pacc[bi][k], p0, p1);
            p0 *= __expf(-0.5f * (s0 + 32.0f));
            p1 *= __expf(-0.5f * (s1 + 32.0f));
            pacc[bi][k] = pk2(p0, p1);
            sacc[bi][k] = pk2(0.f, 0.f);
        }

    // second half: d = 32..63
    #pragma unroll 1
    for (int dblk = 32; dblk < 64; dblk += 4)
        do_dblk(xrow, arow, brow, dblk, M1, sacc, pacc);

    // epilogue
    float* orow = out + (long)(b0 + bg * 2) * N + n0 + ng * 8;
    #pragma unroll
    for (int bi = 0; bi < 2; bi++) {
        float h[8];
        #pragma unroll
        for (int k = 0; k < 4; k++) {
            float s0, s1, p0, p1;
            upk2(sacc[bi][k], s0, s1);
            upk2(pacc[bi][k], p0, p1);
            h[2 * k]     = p0 * __expf(-0.5f * (s0 + 32.0f));
            h[2 * k + 1] = p1 * __expf(-0.5f * (s1 + 32.0f));
        }
        float4 v0 = {h[0], h[1], h[2], h[3]};
        float4 v1 = {h[4], h[5], h[6], h[7]};
        *reinterpret_cast<float4*>(orow + (long)bi * N)     = v0;
        *reinterpret_cast<float4*>(orow + (long)bi * N + 4) = v1;
    }
}

extern "C" void kernel_launch(void* const* d_in, const int* in_sizes, int n_in,
                              void* d_out, int out_size)
{
    const float* x       = (const float*)d_in[0];
    const float* centers = (const float*)d_in[1];
    const float* scales  = (const float*)d_in[2];
    float* out = (float*)d_out;

    const int B = in_sizes[0] / D_DIM;   // 8192
    const int N = in_sizes[1] / D_DIM;   // 512

    const int smem_bytes = (BT * XSTRIDE + 2 * D_DIM * ASTRIDE) * sizeof(float); // 43520
    static bool attr_set = false;
    if (!attr_set) {
        cudaFuncSetAttribute(wavelet_kernel,
                             cudaFuncAttributeMaxDynamicSharedMemorySize, smem_bytes);
        attr_set = true;
    }

    dim3 grid(B / BT, N / NT);           // (256, 8) = 2048 blocks
    wavelet_kernel<<<grid, TPB, smem_bytes>>>(x, centers, scales, out, N);
}

// round 7
// speedup vs baseline: 1.4868x; 1.4868x over previous
#include <cuda_runtime.h>
#include <cstdint>

#define D_DIM 64
#define BT 32            // b per block
#define NT 64            // n per block
#define TPB 128
#define XSTRIDE 68       // floats; 16B-aligned, conflict-free
#define ASTRIDE 68
#define AROWS 66         // 64 + 2 pad rows: pipeline prefetches d=64,65 harmlessly

// ---- packed f32x2 helpers (Blackwell FFMA2) ----
__device__ __forceinline__ uint64_t pk2(float lo, float hi) {
    uint64_t r; asm("mov.b64 %0, {%1, %2};" : "=l"(r) : "f"(lo), "f"(hi)); return r;
}
__device__ __forceinline__ void upk2(uint64_t v, float& lo, float& hi) {
    asm("mov.b64 {%0, %1}, %2;" : "=f"(lo), "=f"(hi) : "l"(v));
}
__device__ __forceinline__ uint64_t fma2(uint64_t a, uint64_t b, uint64_t c) {
    uint64_t d; asm("fma.rn.f32x2 %0, %1, %2, %3;" : "=l"(d) : "l"(a), "l"(b), "l"(c)); return d;
}
__device__ __forceinline__ uint64_t mul2(uint64_t a, uint64_t b) {
    uint64_t d; asm("mul.rn.f32x2 %0, %1, %2;" : "=l"(d) : "l"(a), "l"(b)); return d;
}
__device__ __forceinline__ uint64_t add2(uint64_t a, uint64_t b) {
    uint64_t d; asm("add.rn.f32x2 %0, %1, %2;" : "=l"(d) : "l"(a), "l"(b)); return d;
}

extern __shared__ float smem_dyn[];

// Load one d-pair (d, d+1) of A/B coefficients (2 packed n-pairs each) into a buffer.
__device__ __forceinline__ void loadpair(const float* __restrict__ arow,
                                         const float* __restrict__ brow,
                                         int d, uint64_t (&A)[4], uint64_t (&B)[4])
{
    const ulonglong2 a0 = *reinterpret_cast<const ulonglong2*>(arow + (d)     * ASTRIDE);
    const ulonglong2 a1 = *reinterpret_cast<const ulonglong2*>(arow + (d + 1) * ASTRIDE);
    const ulonglong2 b0 = *reinterpret_cast<const ulonglong2*>(brow + (d)     * ASTRIDE);
    const ulonglong2 b1 = *reinterpret_cast<const ulonglong2*>(brow + (d + 1) * ASTRIDE);
    A[0] = a0.x; A[1] = a0.y; A[2] = a1.x; A[3] = a1.y;
    B[0] = b0.x; B[1] = b0.y; B[2] = b1.x; B[3] = b1.y;
}

// Compute one d-pair using buffer (A,B). xs[bi][0..1] are the two x scalars.
__device__ __forceinline__ void comppair(const uint64_t (&A)[4], const uint64_t (&B)[4],
                                         const float (&xs)[4][2], uint64_t M1,
                                         uint64_t (&sacc)[4][2], uint64_t (&pacc)[4][2])
{
    #pragma unroll
    for (int dd = 0; dd < 2; dd++) {
        #pragma unroll
        for (int bi = 0; bi < 4; bi++) {
            const uint64_t xp = pk2(xs[bi][dd], xs[bi][dd]);
            #pragma unroll
            for (int k = 0; k < 2; k++) {
                uint64_t z = fma2(xp, A[2 * dd + k], B[2 * dd + k]);
                uint64_t w = fma2(z, z, M1);           // z^2 - 1
                sacc[bi][k] = add2(sacc[bi][k], w);    // sum z^2 = sum w + count
                pacc[bi][k] = mul2(pacc[bi][k], w);
            }
        }
    }
}

__global__ __launch_bounds__(TPB, 5)
void wavelet_kernel(const float* __restrict__ x,
                    const float* __restrict__ centers,
                    const float* __restrict__ scales,
                    float* __restrict__ out, int N)
{
    float* sx = smem_dyn;                     // [BT][XSTRIDE]
    float* sa = sx + BT * XSTRIDE;            // [AROWS][ASTRIDE]  1/s  (d-major)
    float* sb = sa + AROWS * ASTRIDE;         // [AROWS][ASTRIDE]  -c/s

    const int tid = threadIdx.x;
    const int b0 = blockIdx.x * BT;
    const int n0 = blockIdx.y * NT;

    // x tile
    #pragma unroll
    for (int i = tid; i < BT * D_DIM; i += TPB) {
        int r = i >> 6, c = i & 63;
        sx[r * XSTRIDE + c] = x[(b0 + r) * D_DIM + c];
    }
    // a/b tiles transposed to [d][n]
    #pragma unroll
    for (int i = tid; i < NT * D_DIM; i += TPB) {
        int d = i & 63, n = i >> 6;
        int g = (n0 + n) * D_DIM + d;
        float inv = 1.0f / scales[g];
        sa[d * ASTRIDE + n] = inv;
        sb[d * ASTRIDE + n] = -centers[g] * inv;
    }
    __syncthreads();

    const int ng = tid & 15;   // 4 n's at ng*4 (2 packed pairs)
    const int bg = tid >> 4;   // 4 b's at bg*4

    const float* xbase = sx + (bg * 4) * XSTRIDE;
    const float* arow  = sa + ng * 4;
    const float* brow  = sb + ng * 4;

    const uint64_t M1 = pk2(-1.0f, -1.0f);
    uint64_t sacc[4][2], pacc[4][2];
    #pragma unroll
    for (int bi = 0; bi < 4; bi++)
        #pragma unroll
        for (int k = 0; k < 2; k++) { sacc[bi][k] = pk2(0.f, 0.f); pacc[bi][k] = pk2(1.f, 1.f); }

    // double-buffered coefficient registers
    uint64_t A0[4], B0[4], A1[4], B1[4];
    loadpair(arow, brow, 0, A0, B0);          // prologue: pair (0,1)

    #pragma unroll
    for (int half = 0; half < 2; half++) {
        #pragma unroll 2
        for (int q = 0; q < 8; q++) {
            const int d0 = half * 32 + q * 4;

            // x for this quad (4 d's x 4 b's)
            float xs01[4][2], xs23[4][2];
            #pragma unroll
            for (int bi = 0; bi < 4; bi++) {
                float4 v = *reinterpret_cast<const float4*>(xbase + bi * XSTRIDE + d0);
                xs01[bi][0] = v.x; xs01[bi][1] = v.y;
                xs23[bi][0] = v.z; xs23[bi][1] = v.w;
            }

            // prefetch pair (d0+2,d0+3) into buf1, compute pair (d0,d0+1) from buf0
            loadpair(arow, brow, d0 + 2, A1, B1);
            comppair(A0, B0, xs01, M1, sacc, pacc);

            // prefetch pair (d0+4,d0+5) into buf0 (overruns into pad rows at the end),
            // compute pair (d0+2,d0+3) from buf1
            loadpair(arow, brow, d0 + 4, A0, B0);
            comppair(A1, B1, xs23, M1, sacc, pacc);
        }

        if (half == 0) {
            // range-control fold: Gaussian factor for first 32 dims
            #pragma unroll
            for (int bi = 0; bi < 4; bi++)
                #pragma unroll
                for (int k = 0; k < 2; k++) {
                    float s0, s1, p0, p1;
                    upk2(sacc[bi][k], s0, s1);
                    upk2(pacc[bi][k], p0, p1);
                    p0 *= __expf(-0.5f * (s0 + 32.0f));
                    p1 *= __expf(-0.5f * (s1 + 32.0f));
                    pacc[bi][k] = pk2(p0, p1);
                    sacc[bi][k] = pk2(0.f, 0.f);
                }
        }
    }

    // epilogue
    float* orow = out + (long)(b0 + bg * 4) * N + n0 + ng * 4;
    #pragma unroll
    for (int bi = 0; bi < 4; bi++) {
        float h[4];
        #pragma unroll
        for (int k = 0; k < 2; k++) {
            float s0, s1, p0, p1;
            upk2(sacc[bi][k], s0, s1);
            upk2(pacc[bi][k], p0, p1);
            h[2 * k]     = p0 * __expf(-0.5f * (s0 + 32.0f));
            h[2 * k + 1] = p1 * __expf(-0.5f * (s1 + 32.0f));
        }
        float4 v = {h[0], h[1], h[2], h[3]};
        *reinterpret_cast<float4*>(orow + (long)bi * N) = v;
    }
}

extern "C" void kernel_launch(void* const* d_in, const int* in_sizes, int n_in,
                              void* d_out, int out_size)
{
    const float* x       = (const float*)d_in[0];
    const float* centers = (const float*)d_in[1];
    const float* scales  = (const float*)d_in[2];
    float* out = (float*)d_out;

    const int B = in_sizes[0] / D_DIM;   // 8192
    const int N = in_sizes[1] / D_DIM;   // 512

    const int smem_bytes = (BT * XSTRIDE + 2 * AROWS * ASTRIDE) * sizeof(float); // 44608
    static bool attr_set = false;
    if (!attr_set) {
        cudaFuncSetAttribute(wavelet_kernel,
                             cudaFuncAttributeMaxDynamicSharedMemorySize, smem_bytes);
        attr_set = true;
    }

    dim3 grid(B / BT, N / NT);           // (256, 8) = 2048 blocks
    wavelet_kernel<<<grid, TPB, smem_bytes>>>(x, centers, scales, out, N);
}

// round 8
// speedup vs baseline: 1.7419x; 1.1716x over previous
#include <cuda_runtime.h>
#include <cstdint>

#define D_DIM 64
#define BT 64            // b per block
#define NT 64            // n per block
#define TPB 256
#define XSTRIDE 68       // floats; 16B-aligned row stride, conflict-free
#define ASTRIDE 68

// ---- packed f32x2 helpers (Blackwell FFMA2 path) ----
__device__ __forceinline__ uint64_t pk2(float lo, float hi) {
    uint64_t r; asm("mov.b64 %0, {%1, %2};" : "=l"(r) : "f"(lo), "f"(hi)); return r;
}
__device__ __forceinline__ void upk2(uint64_t v, float& lo, float& hi) {
    asm("mov.b64 {%0, %1}, %2;" : "=f"(lo), "=f"(hi) : "l"(v));
}
__device__ __forceinline__ uint64_t fma2(uint64_t a, uint64_t b, uint64_t c) {
    uint64_t d; asm("fma.rn.f32x2 %0, %1, %2, %3;" : "=l"(d) : "l"(a), "l"(b), "l"(c)); return d;
}
__device__ __forceinline__ uint64_t mul2(uint64_t a, uint64_t b) {
    uint64_t d; asm("mul.rn.f32x2 %0, %1, %2;" : "=l"(d) : "l"(a), "l"(b)); return d;
}

extern __shared__ float smem_dyn[];

// One 4-dim block: 4 b x 4 n per thread (2 packed n-pairs).
// Sum accumulation uses SCALAR FADD on the halves of w (probe: does FADD
// issue on the alu pipe, freeing fma-pipe sub-slots?).
__device__ __forceinline__ void do_dblk(const float* __restrict__ xrow,
                                        const float* __restrict__ arow,
                                        const float* __restrict__ brow,
                                        int dblk, uint64_t M1,
                                        float (&s0)[4][2], float (&s1)[4][2],
                                        uint64_t (&pacc)[4][2])
{
    float xq[4][4];
    #pragma unroll
    for (int bi = 0; bi < 4; bi++) {
        float4 v = *reinterpret_cast<const float4*>(xrow + bi * XSTRIDE + dblk);
        xq[bi][0] = v.x; xq[bi][1] = v.y; xq[bi][2] = v.z; xq[bi][3] = v.w;
    }
    #pragma unroll
    for (int dd = 0; dd < 4; dd++) {
        const int off = (dblk + dd) * ASTRIDE;
        const ulonglong2 av = *reinterpret_cast<const ulonglong2*>(arow + off);
        const ulonglong2 bv = *reinterpret_cast<const ulonglong2*>(brow + off);
        const uint64_t A[2]  = {av.x, av.y};
        const uint64_t Bv[2] = {bv.x, bv.y};
        #pragma unroll
        for (int bi = 0; bi < 4; bi++) {
            const uint64_t xp = pk2(xq[bi][dd], xq[bi][dd]);
            #pragma unroll
            for (int k = 0; k < 2; k++) {
                uint64_t z = fma2(xp, A[k], Bv[k]);
                uint64_t w = fma2(z, z, M1);          // z^2 - 1
                float w0, w1;
                upk2(w, w0, w1);                      // pair-alias, expect no MOVs
                s0[bi][k] += w0;                      // scalar FADD (alu-pipe probe)
                s1[bi][k] += w1;                      // sum z^2 = sum w + count
                pacc[bi][k] = mul2(pacc[bi][k], w);
            }
        }
    }
}

__global__ __launch_bounds__(TPB, 3)
void wavelet_kernel(const float* __restrict__ x,
                    const float* __restrict__ centers,
                    const float* __restrict__ scales,
                    float* __restrict__ out, int N)
{
    float* sx = smem_dyn;                   // [BT][XSTRIDE]  b-major
    float* sa = sx + BT * XSTRIDE;          // [D][ASTRIDE]   d-major: 1/s
    float* sb = sa + D_DIM * ASTRIDE;       // [D][ASTRIDE]   -c/s

    const int tid = threadIdx.x;
    const int b0 = blockIdx.x * BT;
    const int n0 = blockIdx.y * NT;

    // x tile (coalesced)
    #pragma unroll 2
    for (int i = tid; i < BT * D_DIM; i += TPB) {
        int r = i >> 6, c = i & 63;
        sx[r * XSTRIDE + c] = x[(b0 + r) * D_DIM + c];
    }
    // a/b tiles, transposed to [d][n]
    #pragma unroll 4
    for (int i = tid; i < NT * D_DIM; i += TPB) {
        int d = i & 63, n = i >> 6;
        int g = (n0 + n) * D_DIM + d;
        float inv = 1.0f / scales[g];
        sa[d * ASTRIDE + n] = inv;
        sb[d * ASTRIDE + n] = -centers[g] * inv;
    }
    __syncthreads();

    const int ng = tid & 15;   // 4 n's at ng*4
    const int bg = tid >> 4;   // 4 b's at bg*4

    const float* xrow = sx + (bg * 4) * XSTRIDE;
    const float* arow = sa + ng * 4;
    const float* brow = sb + ng * 4;

    const uint64_t M1 = pk2(-1.0f, -1.0f);
    float s0[4][2], s1[4][2];
    uint64_t pacc[4][2];
    #pragma unroll
    for (int bi = 0; bi < 4; bi++)
        #pragma unroll
        for (int k = 0; k < 2; k++) {
            s0[bi][k] = 0.0f; s1[bi][k] = 0.0f;
            pacc[bi][k] = pk2(1.f, 1.f);
        }

    // first half: d = 0..31
    #pragma unroll 1
    for (int dblk = 0; dblk < 32; dblk += 4)
        do_dblk(xrow, arow, brow, dblk, M1, s0, s1, pacc);

    // range-control fold: Gaussian factor for first 32 dims
    #pragma unroll
    for (int bi = 0; bi < 4; bi++)
        #pragma unroll
        for (int k = 0; k < 2; k++) {
            float p0, p1;
            upk2(pacc[bi][k], p0, p1);
            p0 *= __expf(-0.5f * (s0[bi][k] + 32.0f));
            p1 *= __expf(-0.5f * (s1[bi][k] + 32.0f));
            pacc[bi][k] = pk2(p0, p1);
            s0[bi][k] = 0.0f; s1[bi][k] = 0.0f;
        }

    // second half: d = 32..63
    #pragma unroll 1
    for (int dblk = 32; dblk < 64; dblk += 4)
        do_dblk(xrow, arow, brow, dblk, M1, s0, s1, pacc);

    // epilogue
    float* orow = out + (long)(b0 + bg * 4) * N + n0 + ng * 4;
    #pragma unroll
    for (int bi = 0; bi < 4; bi++) {
        float h[4];
        #pragma unroll
        for (int k = 0; k < 2; k++) {
            float p0, p1;
            upk2(pacc[bi][k], p0, p1);
            h[2 * k]     = p0 * __expf(-0.5f * (s0[bi][k] + 32.0f));
            h[2 * k + 1] = p1 * __expf(-0.5f * (s1[bi][k] + 32.0f));
        }
        float4 v = {h[0], h[1], h[2], h[3]};
        *reinterpret_cast<float4*>(orow + (long)bi * N) = v;
    }
}

extern "C" void kernel_launch(void* const* d_in, const int* in_sizes, int n_in,
                              void* d_out, int out_size)
{
    const float* x       = (const float*)d_in[0];
    const float* centers = (const float*)d_in[1];
    const float* scales  = (const float*)d_in[2];
    float* out = (float*)d_out;

    const int B = in_sizes[0] / D_DIM;   // 8192
    const int N = in_sizes[1] / D_DIM;   // 512

    const int smem_bytes = (BT * XSTRIDE + 2 * D_DIM * ASTRIDE) * sizeof(float); // 52224
    static bool attr_set = false;
    if (!attr_set) {
        cudaFuncSetAttribute(wavelet_kernel,
                             cudaFuncAttributeMaxDynamicSharedMemorySize, smem_bytes);
        attr_set = true;
    }

    dim3 grid(B / BT, N / NT);           // (128, 8) = 1024 blocks
    wavelet_kernel<<<grid, TPB, smem_bytes>>>(x, centers, scales, out, N);
}